// round 2
// baseline (speedup 1.0000x reference)
#include <cuda_runtime.h>
#include <cstdint>

#define MAXN 50000
#define DIM 128

// Scratch: hr[r][node][128] for r in 0..7  (204.8 MB, static device global)
__device__ float g_hr[(size_t)8 * MAXN * DIM];

// ---------------------------------------------------------------------------
// Kernel 1: hr[r] = x @ W[r] for r=0..7; r==8 -> d_out = x @ selfW + bias
// BM=64 nodes, BN=128 outs, BK=16. 256 threads, each computes 4x8 micro-tile.
// ---------------------------------------------------------------------------
__global__ void rgcn_gemm(const float* __restrict__ x,
                          const float* __restrict__ w,
                          const float* __restrict__ sw,
                          const float* __restrict__ bias,
                          float* __restrict__ out,
                          int n_nodes) {
    __shared__ float Ws[16][128];      // 8 KB
    __shared__ float Xs[16][64 + 4];   // padded to kill store bank conflicts

    const int tid = threadIdx.x;
    const int tx = tid & 15;   // 16 col groups of 8
    const int ty = tid >> 4;   // 16 row groups of 4
    const int rel = blockIdx.y;
    const float* wr = (rel < 8) ? (w + (size_t)rel * DIM * DIM) : sw;
    const int row0 = blockIdx.x * 64;

    float acc[4][8];
#pragma unroll
    for (int i = 0; i < 4; i++)
#pragma unroll
        for (int j = 0; j < 8; j++) acc[i][j] = 0.0f;

    for (int k0 = 0; k0 < DIM; k0 += 16) {
        // Load W chunk [16 x 128] (fully coalesced)
#pragma unroll
        for (int i = tid; i < 16 * 128; i += 256) {
            int kk = i >> 7, o = i & 127;
            Ws[kk][o] = wr[(size_t)(k0 + kk) * DIM + o];
        }
        // Load X chunk transposed: Xs[k][row]
#pragma unroll
        for (int i = tid; i < 16 * 64; i += 256) {
            int r = i >> 4, kk = i & 15;
            int node = row0 + r;
            Xs[kk][r] = (node < n_nodes) ? x[(size_t)node * DIM + k0 + kk] : 0.0f;
        }
        __syncthreads();

#pragma unroll
        for (int kk = 0; kk < 16; kk++) {
            float4 a4 = *(const float4*)&Xs[kk][ty * 4];
            float4 b0 = *(const float4*)&Ws[kk][tx * 8];
            float4 b1 = *(const float4*)&Ws[kk][tx * 8 + 4];
            float av[4] = {a4.x, a4.y, a4.z, a4.w};
            float bv[8] = {b0.x, b0.y, b0.z, b0.w, b1.x, b1.y, b1.z, b1.w};
#pragma unroll
            for (int i = 0; i < 4; i++)
#pragma unroll
                for (int j = 0; j < 8; j++)
                    acc[i][j] = fmaf(av[i], bv[j], acc[i][j]);
        }
        __syncthreads();
    }

    if (rel < 8) {
        float* dst = g_hr + (size_t)rel * MAXN * DIM;
#pragma unroll
        for (int i = 0; i < 4; i++) {
            int node = row0 + ty * 4 + i;
            if (node < n_nodes) {
                float4 v0 = make_float4(acc[i][0], acc[i][1], acc[i][2], acc[i][3]);
                float4 v1 = make_float4(acc[i][4], acc[i][5], acc[i][6], acc[i][7]);
                *(float4*)&dst[(size_t)node * DIM + tx * 8]     = v0;
                *(float4*)&dst[(size_t)node * DIM + tx * 8 + 4] = v1;
            }
        }
    } else {
        float b0 = bias[tx * 8 + 0], b1 = bias[tx * 8 + 1], b2 = bias[tx * 8 + 2], b3 = bias[tx * 8 + 3];
        float b4 = bias[tx * 8 + 4], b5 = bias[tx * 8 + 5], b6 = bias[tx * 8 + 6], b7 = bias[tx * 8 + 7];
#pragma unroll
        for (int i = 0; i < 4; i++) {
            int node = row0 + ty * 4 + i;
            if (node < n_nodes) {
                float4 v0 = make_float4(acc[i][0] + b0, acc[i][1] + b1, acc[i][2] + b2, acc[i][3] + b3);
                float4 v1 = make_float4(acc[i][4] + b4, acc[i][5] + b5, acc[i][6] + b6, acc[i][7] + b7);
                *(float4*)&out[(size_t)node * DIM + tx * 8]     = v0;
                *(float4*)&out[(size_t)node * DIM + tx * 8 + 4] = v1;
            }
        }
    }
}

// ---------------------------------------------------------------------------
// Kernel 2: one warp per edge. Gather hr[et][src] (512B contiguous),
// red.global.add.v4.f32 into out[dst].
// edge_index / edge_type are int32 (JAX x64 disabled downcasts int64->int32).
// ---------------------------------------------------------------------------
__global__ void rgcn_scatter(const int* __restrict__ ei,
                             const int* __restrict__ et,
                             float* __restrict__ out,
                             int n_edges) {
    int g = blockIdx.x * blockDim.x + threadIdx.x;
    int e = g >> 5;
    int lane = g & 31;
    if (e >= n_edges) return;

    int s = ei[e];
    int d = ei[n_edges + e];
    int r = et[e];

    const float* src = g_hr + ((size_t)r * MAXN + (size_t)s) * DIM + lane * 4;
    float4 v = *(const float4*)src;
    float* p = out + (size_t)d * DIM + lane * 4;
    asm volatile("red.global.add.v4.f32 [%0], {%1, %2, %3, %4};"
                 :: "l"(p), "f"(v.x), "f"(v.y), "f"(v.z), "f"(v.w)
                 : "memory");
}

// ---------------------------------------------------------------------------
// Kernel 3: in-place ReLU (float4)
// ---------------------------------------------------------------------------
__global__ void rgcn_relu(float* __restrict__ out, int n4) {
    int i = blockIdx.x * blockDim.x + threadIdx.x;
    if (i < n4) {
        float4 v = ((float4*)out)[i];
        v.x = fmaxf(v.x, 0.0f);
        v.y = fmaxf(v.y, 0.0f);
        v.z = fmaxf(v.z, 0.0f);
        v.w = fmaxf(v.w, 0.0f);
        ((float4*)out)[i] = v;
    }
}

// ---------------------------------------------------------------------------
// Launch. Inputs (metadata order): x, weight, self_loop_weight, bias,
// edge_index (int32 [2,E]), edge_type (int32 [E]), num_entities.
// ---------------------------------------------------------------------------
extern "C" void kernel_launch(void* const* d_in, const int* in_sizes, int n_in,
                              void* d_out, int out_size) {
    const float* x    = (const float*)d_in[0];
    const float* w    = (const float*)d_in[1];
    const float* sw   = (const float*)d_in[2];
    const float* bias = (const float*)d_in[3];
    const int* ei = (const int*)d_in[4];
    const int* et = (const int*)d_in[5];

    int n_nodes = in_sizes[0] / DIM;
    int n_edges = in_sizes[5];
    float* out = (float*)d_out;

    // 1) GEMMs: 8 relations into g_hr, relation 8 = self-loop + bias into out
    dim3 g1((n_nodes + 63) / 64, 9);
    rgcn_gemm<<<g1, 256>>>(x, w, sw, bias, out, n_nodes);

    // 2) Edge scatter: one warp per edge
    long long total_threads = (long long)n_edges * 32;
    int blocks = (int)((total_threads + 255) / 256);
    rgcn_scatter<<<blocks, 256>>>(ei, et, out, n_edges);

    // 3) ReLU
    int n4 = n_nodes * DIM / 4;
    rgcn_relu<<<(n4 + 255) / 256, 256>>>(out, n4);
}

// round 4
// speedup vs baseline: 3.5202x; 3.5202x over previous
#include <cuda_runtime.h>
#include <cstdint>

#define DIM 128
#define NPAD 50048          // ceil(50000/128)*128
#define NREL 9              // 8 relations + self-loop

// hr[r][node][128] scratch, r in 0..7  (205 MB static device global)
__device__ float g_hr[(size_t)8 * NPAD * DIM];

// Padded smem strides (floats). Chosen so fragment loads are conflict-free:
// A: bank = (4*row + k) mod 32 (bijective over warp); B: (8*k + n) mod 32.
#define XS_STRIDE 132
#define WS_STRIDE 136
#define SMEM_FLOATS (128 * XS_STRIDE + 2 * 128 * WS_STRIDE)
#define SMEM_BYTES (SMEM_FLOATS * 4)   // 206848 B

__device__ __forceinline__ uint32_t f2tf32(float f) {
    uint32_t o;
    asm("cvt.rna.tf32.f32 %0, %1;" : "=r"(o) : "f"(f));
    return o;
}

#define MMA_TF32(d, a, b0, b1)                                                  \
    asm volatile("mma.sync.aligned.m16n8k8.row.col.f32.tf32.tf32.f32 "          \
                 "{%0,%1,%2,%3}, {%4,%5,%6,%7}, {%8,%9}, {%0,%1,%2,%3};"        \
                 : "+f"((d)[0]), "+f"((d)[1]), "+f"((d)[2]), "+f"((d)[3])       \
                 : "r"((a)[0]), "r"((a)[1]), "r"((a)[2]), "r"((a)[3]),          \
                   "r"(b0), "r"(b1))

__device__ __forceinline__ void cp16(float* s, const float* g) {
    uint32_t sa = (uint32_t)__cvta_generic_to_shared(s);
    asm volatile("cp.async.cg.shared.global [%0], [%1], 16;" :: "r"(sa), "l"(g));
}

// Issue async copy of one 128x128 W matrix into padded smem buffer.
__device__ __forceinline__ void issue_w(float* buf, const float* wr, int tid) {
#pragma unroll
    for (int i = tid; i < 128 * 32; i += 256) {
        int r = i >> 5, c4 = i & 31;
        cp16(buf + r * WS_STRIDE + c4 * 4, wr + r * DIM + c4 * 4);
    }
    asm volatile("cp.async.commit_group;" ::: "memory");
}

// ---------------------------------------------------------------------------
// GEMM: per CTA, 128 node rows x all 9 relations. tf32 mma.sync (m16n8k8).
// rel 0..7 -> g_hr[rel]; rel 8 -> out = X@selfW + bias.
// ---------------------------------------------------------------------------
__global__ void __launch_bounds__(256, 1)
rgcn_gemm_mma(const float* __restrict__ x,
              const float* __restrict__ w,    // [8][128][128] (k-major rows)
              const float* __restrict__ sw,   // [128][128]
              const float* __restrict__ bias,
              float* __restrict__ out,
              int n_nodes) {
    extern __shared__ float smem[];
    float* Xs  = smem;                         // [128][XS_STRIDE] (tf32 bits)
    float* Ws0 = smem + 128 * XS_STRIDE;       // [128][WS_STRIDE]
    float* Ws1 = Ws0 + 128 * WS_STRIDE;

    const int tid = threadIdx.x;
    const int wid = tid >> 5, lane = tid & 31;
    const int row0 = blockIdx.x * 128;
    const int wm = (wid & 3) * 32;   // warp row offset (32 rows)
    const int wn = (wid >> 2) * 64;  // warp col offset (64 cols)

    // Prefetch W[0], W[1] via cp.async (each its own commit group)
    issue_w(Ws0, w, tid);
    issue_w(Ws1, w + DIM * DIM, tid);

    // Fill X tile (convert to tf32 bits once; zero-pad tail rows)
#pragma unroll
    for (int i = tid; i < 128 * 32; i += 256) {
        int r = i >> 5, c4 = i & 31;
        int node = row0 + r;
        float4 v = (node < n_nodes) ? *(const float4*)(x + (size_t)node * DIM + c4 * 4)
                                    : make_float4(0.f, 0.f, 0.f, 0.f);
        uint32_t* d = (uint32_t*)(Xs + r * XS_STRIDE + c4 * 4);
        d[0] = f2tf32(v.x); d[1] = f2tf32(v.y); d[2] = f2tf32(v.z); d[3] = f2tf32(v.w);
    }

    const int lr = lane >> 2;          // 0..7
    const int lk = lane & 3;           // 0..3
    const int lc = (lane & 3) * 2;

    for (int rel = 0; rel < NREL; ++rel) {
        if (rel == NREL - 1) asm volatile("cp.async.wait_group 0;" ::: "memory");
        else                 asm volatile("cp.async.wait_group 1;" ::: "memory");
        __syncthreads();   // W[rel] visible to all; everyone done with buf from rel-2

        const float* Wb = (rel & 1) ? Ws1 : Ws0;

        float c[16][4];
#pragma unroll
        for (int i = 0; i < 16; i++)
#pragma unroll
            for (int j = 0; j < 4; j++) c[i][j] = 0.0f;

#pragma unroll 4
        for (int ks = 0; ks < 16; ks++) {
            const int k0 = ks * 8;
            uint32_t a[2][4];
#pragma unroll
            for (int mt = 0; mt < 2; mt++) {
                const uint32_t* xr = (const uint32_t*)Xs + (wm + mt * 16 + lr) * XS_STRIDE + k0 + lk;
                a[mt][0] = xr[0];
                a[mt][1] = xr[8 * XS_STRIDE];
                a[mt][2] = xr[4];
                a[mt][3] = xr[8 * XS_STRIDE + 4];
            }
#pragma unroll
            for (int nt = 0; nt < 8; nt++) {
                const float* wp = Wb + (k0 + lk) * WS_STRIDE + wn + nt * 8 + lr;
                uint32_t b0 = f2tf32(wp[0]);
                uint32_t b1 = f2tf32(wp[4 * WS_STRIDE]);
                MMA_TF32(c[nt], a[0], b0, b1);
                MMA_TF32(c[8 + nt], a[1], b0, b1);
            }
        }

        __syncthreads();   // all warps finished reading Wb
        if (rel + 2 < NREL) {
            const float* nw = (rel + 2 < 8) ? (w + (size_t)(rel + 2) * DIM * DIM) : sw;
            issue_w((float*)Wb, nw, tid);   // reuse the buffer just consumed... (rel&1 buf)
        }

        // ---- epilogue ----
        if (rel < 8) {
            float* base = g_hr + ((size_t)rel * NPAD + row0) * DIM;
#pragma unroll
            for (int mt = 0; mt < 2; mt++)
#pragma unroll
                for (int nt = 0; nt < 8; nt++) {
                    int r = wm + mt * 16 + lr;
                    int cc = wn + nt * 8 + lc;
                    float* p0 = base + (size_t)r * DIM + cc;
                    float* p1 = base + (size_t)(r + 8) * DIM + cc;
                    *(float2*)p0 = make_float2(c[mt * 8 + nt][0], c[mt * 8 + nt][1]);
                    *(float2*)p1 = make_float2(c[mt * 8 + nt][2], c[mt * 8 + nt][3]);
                }
        } else {
#pragma unroll
            for (int mt = 0; mt < 2; mt++)
#pragma unroll
                for (int nt = 0; nt < 8; nt++) {
                    int r = wm + mt * 16 + lr;
                    int cc = wn + nt * 8 + lc;
                    float b0 = bias[cc], b1 = bias[cc + 1];
                    int g0 = row0 + r, g1 = row0 + r + 8;
                    if (g0 < n_nodes)
                        *(float2*)(out + (size_t)g0 * DIM + cc) =
                            make_float2(c[mt * 8 + nt][0] + b0, c[mt * 8 + nt][1] + b1);
                    if (g1 < n_nodes)
                        *(float2*)(out + (size_t)g1 * DIM + cc) =
                            make_float2(c[mt * 8 + nt][2] + b0, c[mt * 8 + nt][3] + b1);
                }
        }
    }
}

// ---------------------------------------------------------------------------
// Scatter: one warp per edge; gather hr[et][src] (512B), red.v4 into out[dst]
// ---------------------------------------------------------------------------
__global__ void rgcn_scatter(const int* __restrict__ ei,
                             const int* __restrict__ et,
                             float* __restrict__ out,
                             int n_edges) {
    int g = blockIdx.x * blockDim.x + threadIdx.x;
    int e = g >> 5, lane = g & 31;
    if (e >= n_edges) return;
    int s = ei[e];
    int d = ei[n_edges + e];
    int r = et[e];
    const float* src = g_hr + ((size_t)r * NPAD + (size_t)s) * DIM + lane * 4;
    float4 v = *(const float4*)src;
    float* p = out + (size_t)d * DIM + lane * 4;
    asm volatile("red.global.add.v4.f32 [%0], {%1, %2, %3, %4};"
                 :: "l"(p), "f"(v.x), "f"(v.y), "f"(v.z), "f"(v.w) : "memory");
}

__global__ void rgcn_relu(float* __restrict__ out, int n4) {
    int i = blockIdx.x * blockDim.x + threadIdx.x;
    if (i < n4) {
        float4 v = ((float4*)out)[i];
        v.x = fmaxf(v.x, 0.0f); v.y = fmaxf(v.y, 0.0f);
        v.z = fmaxf(v.z, 0.0f); v.w = fmaxf(v.w, 0.0f);
        ((float4*)out)[i] = v;
    }
}

// ---------------------------------------------------------------------------
// Host launch
// ---------------------------------------------------------------------------
extern "C" void kernel_launch(void* const* d_in, const int* in_sizes, int n_in,
                              void* d_out, int out_size) {
    const float* x    = (const float*)d_in[0];
    const float* w    = (const float*)d_in[1];
    const float* sw   = (const float*)d_in[2];
    const float* bias = (const float*)d_in[3];
    const int* ei = (const int*)d_in[4];
    const int* et = (const int*)d_in[5];

    int n_nodes = in_sizes[0] / DIM;
    int n_edges = in_sizes[5];
    float* out = (float*)d_out;

    static int smem_set = 0;
    if (!smem_set) {
        cudaFuncSetAttribute(rgcn_gemm_mma, cudaFuncAttributeMaxDynamicSharedMemorySize,
                             SMEM_BYTES);
        smem_set = 1;
    }

    int nb = (n_nodes + 127) / 128;
    rgcn_gemm_mma<<<nb, 256, SMEM_BYTES>>>(x, w, sw, bias, out, n_nodes);

    long long total_threads = (long long)n_edges * 32;
    int blocks = (int)((total_threads + 255) / 256);
    rgcn_scatter<<<blocks, 256>>>(ei, et, out, n_edges);

    int n4 = n_nodes * DIM / 4;
    rgcn_relu<<<(n4 + 255) / 256, 256>>>(out, n4);
}